// round 10
// baseline (speedup 1.0000x reference)
#include <cuda_runtime.h>
#include <cstdint>

#define BB 256   // batch
#define DD 256   // groups
#define KK 1024  // codes
#define EE 16    // embed dim
#define DECAY 0.999f
#define GAINF 0.001f
#define EPSF 1e-6f

#define NT1 512
#define NQ  4           // in-block K splits
#define KPT (KK / NQ)   // 256 codes per thread
#define BPT 2           // batch rows per thread

typedef unsigned long long u64;

__device__ __forceinline__ u64 fma2(u64 a, u64 b, u64 c) {
    u64 d; asm("fma.rn.f32x2 %0, %1, %2, %3;" : "=l"(d) : "l"(a), "l"(b), "l"(c));
    return d;
}
__device__ __forceinline__ u64 mul2(u64 a, u64 b) {
    u64 d; asm("mul.rn.f32x2 %0, %1, %2;" : "=l"(d) : "l"(a), "l"(b));
    return d;
}
__device__ __forceinline__ float2 upk(u64 v) {
    float2 r; asm("mov.b64 {%0, %1}, %2;" : "=f"(r.x), "=f"(r.y) : "l"(v));
    return r;
}

// smem (floats): cb 16384 | c2h 1024 | red_d 1024 | red_i 1024 | zbuf 1024
//              = 20480 floats = 80 KB -> 2 CTAs/SM (160 KB <= 228 KB)
#define SM1_FLOATS (KK*EE + KK + NQ*BB + NQ*BB + KK)

__global__ __launch_bounds__(NT1, 2)
void vq_fused(const float* __restrict__ cw_q,      // [B, D*E]
              const float* __restrict__ codebook,  // [D, K, E]
              const float* __restrict__ ema,       // [D, K]
              float* __restrict__ out_embed,       // [B, D*E]
              float* __restrict__ out_onehot,      // [B, D, K]
              float* __restrict__ out_cb,          // [D, K, E]
              float* __restrict__ out_ema)         // [D, K]
{
    const int d   = blockIdx.x;
    const int tid = threadIdx.x;

    extern __shared__ float sm[];
    float* cb_s  = sm;                      // KK*EE
    float* c2_s  = cb_s + KK*EE;            // KK  (0.5*||c||^2)
    float* red_d = c2_s + KK;               // NQ*BB
    int*   red_i = (int*)(red_d + NQ*BB);   // NQ*BB
    float* zbuf  = (float*)(red_i + NQ*BB); // KK zeros (one one_hot row)

    // ---- Phase A: start the 1 MB one_hot zero stream ASAP (TMA pipe) ----
    zbuf[tid]       = 0.0f;                 // NT1*2 == KK
    zbuf[tid + NT1] = 0.0f;
    asm volatile("fence.proxy.async.shared::cta;" ::: "memory");
    __syncthreads();
    if (tid < BB) {
        float* grow = out_onehot + (size_t)tid * (DD*KK) + (size_t)d * KK;
        uint32_t zs = (uint32_t)__cvta_generic_to_shared(zbuf);
        asm volatile("cp.async.bulk.global.shared::cta.bulk_group [%0], [%1], %2;"
                     :: "l"(grow), "r"(zs), "r"(KK*4) : "memory");
        asm volatile("cp.async.bulk.commit_group;" ::: "memory");
    }

    // ---- prefetch this thread's 2 x-rows (overlaps all smem phases) ----
    const int b0 = (tid & 127) * BPT;
    const int q  = tid >> 7;              // 0..3
    u64 xp0[EE/2], xp1[EE/2];
    {
        const ulonglong2* xg0 = (const ulonglong2*)(cw_q
                               + (size_t)b0 * (DD*EE) + (size_t)d * EE);
        const ulonglong2* xg1 = (const ulonglong2*)(cw_q
                               + (size_t)(b0+1) * (DD*EE) + (size_t)d * EE);
        #pragma unroll
        for (int i = 0; i < 4; i++) {
            ulonglong2 v0 = xg0[i];
            ulonglong2 v1 = xg1[i];
            xp0[2*i] = v0.x; xp0[2*i+1] = v0.y;
            xp1[2*i] = v1.x; xp1[2*i+1] = v1.y;
        }
    }

    // ---- Phase B: codebook -> smem; out_cb decay base; out_ema decay base ----
    {
        const float4* cbg = (const float4*)(codebook + (size_t)d * KK * EE);
        float4* ob4 = (float4*)(out_cb + (size_t)d * KK * EE);
        float4* cb4 = (float4*)cb_s;
        #pragma unroll
        for (int i = tid; i < KK*EE/4; i += NT1) {
            float4 v = cbg[i];
            cb4[i] = v;
            ob4[i] = make_float4(v.x*DECAY, v.y*DECAY, v.z*DECAY, v.w*DECAY);
        }
        const float* eg = ema + (size_t)d * KK;
        float*       oe = out_ema + (size_t)d * KK;
        oe[tid]       = DECAY * eg[tid];
        oe[tid + NT1] = DECAY * eg[tid + NT1];
    }
    __syncthreads();

    // ---- Phase C: c2h[k] = 0.5*||c_k||^2 ----
    #pragma unroll
    for (int k = tid; k < KK; k += NT1) {
        const float4* row = (const float4*)(cb_s + k*EE);
        float s = 0.0f;
        #pragma unroll
        for (int i = 0; i < EE/4; i++) {
            float4 v = row[i];
            s = fmaf(v.x, v.x, s); s = fmaf(v.y, v.y, s);
            s = fmaf(v.z, v.z, s); s = fmaf(v.w, v.w, s);
        }
        c2_s[k] = 0.5f * s;
    }
    __syncthreads();

    // ---- Phase D: argmin; 2 rows per thread, KPT codes (LDS amortized 2x) ----
    const int k0 = q * KPT;
    float best0 = __int_as_float(0x7f800000);
    float best1 = __int_as_float(0x7f800000);
    int   bi0 = k0, bi1 = k0;

    const ulonglong2* cbp = (const ulonglong2*)cb_s;
    #pragma unroll 2
    for (int k = k0; k < k0 + KPT; k++) {
        ulonglong2 p0 = cbp[k*4+0];
        ulonglong2 p1 = cbp[k*4+1];
        u64 a0 = mul2(xp0[0], p0.x);
        u64 a1 = mul2(xp1[0], p0.x);
        a0 = fma2(xp0[1], p0.y, a0);
        a1 = fma2(xp1[1], p0.y, a1);
        a0 = fma2(xp0[2], p1.x, a0);
        a1 = fma2(xp1[2], p1.x, a1);
        a0 = fma2(xp0[3], p1.y, a0);
        a1 = fma2(xp1[3], p1.y, a1);
        ulonglong2 p2 = cbp[k*4+2];
        ulonglong2 p3 = cbp[k*4+3];
        a0 = fma2(xp0[4], p2.x, a0);
        a1 = fma2(xp1[4], p2.x, a1);
        a0 = fma2(xp0[5], p2.y, a0);
        a1 = fma2(xp1[5], p2.y, a1);
        a0 = fma2(xp0[6], p3.x, a0);
        a1 = fma2(xp1[6], p3.x, a1);
        a0 = fma2(xp0[7], p3.y, a0);
        a1 = fma2(xp1[7], p3.y, a1);

        float c2k = c2_s[k];
        float2 s0 = upk(a0);
        float2 s1 = upk(a1);
        float d0 = c2k - (s0.x + s0.y);   // x^2 dropped: argmin-invariant
        float d1 = c2k - (s1.x + s1.y);
        if (d0 < best0) { best0 = d0; bi0 = k; }
        if (d1 < best1) { best1 = d1; bi1 = k; }
    }
    red_d[q*BB + b0]     = best0;
    red_i[q*BB + b0]     = bi0;
    red_d[q*BB + b0 + 1] = best1;
    red_i[q*BB + b0 + 1] = bi1;
    __syncthreads();

    // ---- Phase E+F: combine splits (ascending q => first-min ties) + epilogue ----
    if (tid < BB) {
        const int b = tid;
        float fb = red_d[b];
        int   fi = red_i[b];
        #pragma unroll
        for (int qq = 1; qq < NQ; qq++) {
            float dq = red_d[qq*BB + b];
            if (dq < fb) { fb = dq; fi = red_i[qq*BB + b]; }
        }

        // cw_embed[b, d] = codebook[d, fi]  (from resident smem copy)
        {
            const float4* src = (const float4*)(cb_s + fi*EE);
            float4 v0 = src[0], v1 = src[1], v2 = src[2], v3 = src[3];
            float4* eo = (float4*)(out_embed + (size_t)b * (DD*EE) + (size_t)d * EE);
            eo[0] = v0; eo[1] = v1; eo[2] = v2; eo[3] = v3;
        }

        // this thread's own zero-row bulk store must land before its '1'
        asm volatile("cp.async.bulk.wait_group 0;" ::: "memory");
        out_onehot[(size_t)b * (DD*KK) + (size_t)d * KK + fi] = 1.0f;

        // EMA updates against this block's decay bases (same-block order,
        // pattern validated in R3)
        const float em  = ema[(size_t)d * KK + fi];
        const float den = GAINF / (em + EPSF);
        const float* xb = cw_q + (size_t)b * (DD*EE) + (size_t)d * EE;
        float* dst = out_cb + (size_t)d * KK * EE + (size_t)fi * EE;
        #pragma unroll
        for (int e = 0; e < EE; e++)
            atomicAdd(&dst[e], den * xb[e]);
        atomicAdd(&out_ema[(size_t)d * KK + fi], GAINF);
    }
}

extern "C" void kernel_launch(void* const* d_in, const int* in_sizes, int n_in,
                              void* d_out, int out_size)
{
    const float* cw_q     = (const float*)d_in[0];
    const float* codebook = (const float*)d_in[1];
    const float* ema      = (const float*)d_in[2];

    float* out        = (float*)d_out;
    float* out_embed  = out;                                   // B*D*E
    float* out_onehot = out_embed  + (size_t)BB * DD * EE;     // B*D*K
    float* out_cb     = out_onehot + (size_t)BB * DD * KK;     // D*K*E
    float* out_ema    = out_cb     + (size_t)DD * KK * EE;     // D*K

    const size_t sm1 = (size_t)SM1_FLOATS * sizeof(float);
    cudaFuncSetAttribute(vq_fused, cudaFuncAttributeMaxDynamicSharedMemorySize, (int)sm1);

    vq_fused<<<DD, NT1, sm1>>>(cw_q, codebook, ema,
                               out_embed, out_onehot, out_cb, out_ema);
}

// round 11
// speedup vs baseline: 1.1339x; 1.1339x over previous
#include <cuda_runtime.h>
#include <cstdint>

#define BB 256   // batch
#define DD 256   // groups
#define KK 1024  // codes
#define EE 16    // embed dim
#define DECAY 0.999f
#define GAINF 0.001f
#define EPSF 1e-6f

#define NT1 512
#define NH  2           // batch halves (one block each)
#define RPB (BB / NH)   // 128 rows per block
#define NQ  8           // in-block K splits
#define KPT (KK / NQ)   // 128 codes per thread
#define BPT 2           // batch rows per thread

typedef unsigned long long u64;

__device__ __forceinline__ u64 fma2(u64 a, u64 b, u64 c) {
    u64 d; asm("fma.rn.f32x2 %0, %1, %2, %3;" : "=l"(d) : "l"(a), "l"(b), "l"(c));
    return d;
}
__device__ __forceinline__ u64 mul2(u64 a, u64 b) {
    u64 d; asm("mul.rn.f32x2 %0, %1, %2;" : "=l"(d) : "l"(a), "l"(b));
    return d;
}
__device__ __forceinline__ float2 upk(u64 v) {
    float2 r; asm("mov.b64 {%0, %1}, %2;" : "=f"(r.x), "=f"(r.y) : "l"(v));
    return r;
}

// ---- k0: decay bases (overlapped under k1 via PDL) ----
__global__ __launch_bounds__(512)
void vq_k0(const float* __restrict__ codebook,
           const float* __restrict__ ema,
           float* __restrict__ out_cb,
           float* __restrict__ out_ema)
{
#if __CUDA_ARCH__ >= 900
    cudaTriggerProgrammaticLaunchCompletion();
#endif
    const int d   = blockIdx.x;
    const int tid = threadIdx.x;
    const float4* s = (const float4*)(codebook + (size_t)d * KK * EE);
    float4*       o = (float4*)(out_cb   + (size_t)d * KK * EE);
    #pragma unroll
    for (int i = tid; i < KK*EE/4; i += 512) {
        float4 v = s[i];
        o[i] = make_float4(v.x*DECAY, v.y*DECAY, v.z*DECAY, v.w*DECAY);
    }
    const float* eg = ema + (size_t)d * KK;
    float*       oe = out_ema + (size_t)d * KK;
    oe[tid]       = DECAY * eg[tid];
    oe[tid + 512] = DECAY * eg[tid + 512];
}

// k1 smem (floats): cb 16384 | c2h 1024 | red_d 1024 | red_i 1024 | zbuf 1024
//                 = 20480 floats = 80 KB -> 2 CTAs/SM
#define SM1_FLOATS (KK*EE + KK + NQ*RPB + NQ*RPB + KK)

__global__ __launch_bounds__(NT1, 2)
void vq_k1(const float* __restrict__ cw_q,      // [B, D*E]
           const float* __restrict__ codebook,  // [D, K, E]
           const float* __restrict__ ema,       // [D, K]
           float* __restrict__ out_embed,       // [B, D*E]
           float* __restrict__ out_onehot,      // [B, D, K]
           float* __restrict__ out_cb,          // [D, K, E]
           float* __restrict__ out_ema)         // [D, K]
{
    const int d   = blockIdx.x >> 1;
    const int h   = blockIdx.x & 1;         // batch half
    const int tid = threadIdx.x;

    extern __shared__ float sm[];
    float* cb_s  = sm;                      // KK*EE
    float* c2_s  = cb_s + KK*EE;            // KK  (0.5*||c||^2)
    float* red_d = c2_s + KK;               // NQ*RPB
    int*   red_i = (int*)(red_d + NQ*RPB);  // NQ*RPB
    float* zbuf  = (float*)(red_i + NQ*RPB);// KK zeros

    // ---- Phase A: one_hot zero stream for this block's 128 rows (TMA pipe) ----
    zbuf[tid]       = 0.0f;                 // NT1*2 == KK
    zbuf[tid + NT1] = 0.0f;
    asm volatile("fence.proxy.async.shared::cta;" ::: "memory");
    __syncthreads();
    if (tid < RPB) {
        const int b = h * RPB + tid;
        float* grow = out_onehot + (size_t)b * (DD*KK) + (size_t)d * KK;
        uint32_t zs = (uint32_t)__cvta_generic_to_shared(zbuf);
        asm volatile("cp.async.bulk.global.shared::cta.bulk_group [%0], [%1], %2;"
                     :: "l"(grow), "r"(zs), "r"(KK*4) : "memory");
        asm volatile("cp.async.bulk.commit_group;" ::: "memory");
    }

    // ---- prefetch this thread's 2 x-rows ----
    const int rg = tid & 63;                // row group
    const int q  = tid >> 6;                // 0..7 K split
    const int b0 = h * RPB + rg * BPT;
    u64 xp0[EE/2], xp1[EE/2];
    {
        const ulonglong2* xg0 = (const ulonglong2*)(cw_q
                               + (size_t)b0 * (DD*EE) + (size_t)d * EE);
        const ulonglong2* xg1 = (const ulonglong2*)(cw_q
                               + (size_t)(b0+1) * (DD*EE) + (size_t)d * EE);
        #pragma unroll
        for (int i = 0; i < 4; i++) {
            ulonglong2 v0 = xg0[i];
            ulonglong2 v1 = xg1[i];
            xp0[2*i] = v0.x; xp0[2*i+1] = v0.y;
            xp1[2*i] = v1.x; xp1[2*i+1] = v1.y;
        }
    }

    // ---- Phase B: codebook -> smem (read-only; bases handled by k0) ----
    {
        const float4* cbg = (const float4*)(codebook + (size_t)d * KK * EE);
        float4* cb4 = (float4*)cb_s;
        #pragma unroll
        for (int i = tid; i < KK*EE/4; i += NT1)
            cb4[i] = cbg[i];
    }
    __syncthreads();

    // ---- Phase C: c2h[k] = 0.5*||c_k||^2 ----
    #pragma unroll
    for (int k = tid; k < KK; k += NT1) {
        const float4* row = (const float4*)(cb_s + k*EE);
        float s = 0.0f;
        #pragma unroll
        for (int i = 0; i < EE/4; i++) {
            float4 v = row[i];
            s = fmaf(v.x, v.x, s); s = fmaf(v.y, v.y, s);
            s = fmaf(v.z, v.z, s); s = fmaf(v.w, v.w, s);
        }
        c2_s[k] = 0.5f * s;
    }
    __syncthreads();

    // ---- Phase D: argmin; 2 rows per thread over KPT codes ----
    const int k0 = q * KPT;
    float best0 = __int_as_float(0x7f800000);
    float best1 = __int_as_float(0x7f800000);
    int   bi0 = k0, bi1 = k0;

    const ulonglong2* cbp = (const ulonglong2*)cb_s;
    #pragma unroll 2
    for (int k = k0; k < k0 + KPT; k++) {
        ulonglong2 p0 = cbp[k*4+0];
        ulonglong2 p1 = cbp[k*4+1];
        u64 a0 = mul2(xp0[0], p0.x);
        u64 a1 = mul2(xp1[0], p0.x);
        a0 = fma2(xp0[1], p0.y, a0);
        a1 = fma2(xp1[1], p0.y, a1);
        a0 = fma2(xp0[2], p1.x, a0);
        a1 = fma2(xp1[2], p1.x, a1);
        a0 = fma2(xp0[3], p1.y, a0);
        a1 = fma2(xp1[3], p1.y, a1);
        ulonglong2 p2 = cbp[k*4+2];
        ulonglong2 p3 = cbp[k*4+3];
        a0 = fma2(xp0[4], p2.x, a0);
        a1 = fma2(xp1[4], p2.x, a1);
        a0 = fma2(xp0[5], p2.y, a0);
        a1 = fma2(xp1[5], p2.y, a1);
        a0 = fma2(xp0[6], p3.x, a0);
        a1 = fma2(xp1[6], p3.x, a1);
        a0 = fma2(xp0[7], p3.y, a0);
        a1 = fma2(xp1[7], p3.y, a1);

        float c2k = c2_s[k];
        float2 s0 = upk(a0);
        float2 s1 = upk(a1);
        float d0 = c2k - (s0.x + s0.y);   // x^2 dropped: argmin-invariant
        float d1 = c2k - (s1.x + s1.y);
        if (d0 < best0) { best0 = d0; bi0 = k; }
        if (d1 < best1) { best1 = d1; bi1 = k; }
    }
    const int r0 = rg * BPT;                 // row index within block [0,128)
    red_d[q*RPB + r0]     = best0;
    red_i[q*RPB + r0]     = bi0;
    red_d[q*RPB + r0 + 1] = best1;
    red_i[q*RPB + r0 + 1] = bi1;
    __syncthreads();

    // ---- Phase E: combine K-splits (ascending q => first-min ties) + epilogue ----
    if (tid < RPB) {
        const int b = h * RPB + tid;         // global batch row
        float fb = red_d[tid];
        int   fi = red_i[tid];
        #pragma unroll
        for (int qq = 1; qq < NQ; qq++) {
            float dq = red_d[qq*RPB + tid];
            if (dq < fb) { fb = dq; fi = red_i[qq*RPB + tid]; }
        }

        // cw_embed[b, d] = codebook[d, fi]  (from resident smem copy)
        {
            const float4* src = (const float4*)(cb_s + fi*EE);
            float4 v0 = src[0], v1 = src[1], v2 = src[2], v3 = src[3];
            float4* eo = (float4*)(out_embed + (size_t)b * (DD*EE) + (size_t)d * EE);
            eo[0] = v0; eo[1] = v1; eo[2] = v2; eo[3] = v3;
        }

        // this thread's own zero-row bulk store must land before its '1'
        asm volatile("cp.async.bulk.wait_group 0;" ::: "memory");
        out_onehot[(size_t)b * (DD*KK) + (size_t)d * KK + fi] = 1.0f;

#if __CUDA_ARCH__ >= 900
        // wait for k0's decay bases before adding EMA contributions
        cudaGridDependencySynchronize();
#endif
        const float em  = ema[(size_t)d * KK + fi];
        const float den = GAINF / (em + EPSF);
        const float* xb = cw_q + (size_t)b * (DD*EE) + (size_t)d * EE;
        float* dst = out_cb + (size_t)d * KK * EE + (size_t)fi * EE;
        #pragma unroll
        for (int e = 0; e < EE; e++)
            atomicAdd(&dst[e], den * xb[e]);
        atomicAdd(&out_ema[(size_t)d * KK + fi], GAINF);
    }
}

extern "C" void kernel_launch(void* const* d_in, const int* in_sizes, int n_in,
                              void* d_out, int out_size)
{
    const float* cw_q     = (const float*)d_in[0];
    const float* codebook = (const float*)d_in[1];
    const float* ema      = (const float*)d_in[2];

    float* out        = (float*)d_out;
    float* out_embed  = out;                                   // B*D*E
    float* out_onehot = out_embed  + (size_t)BB * DD * EE;     // B*D*K
    float* out_cb     = out_onehot + (size_t)BB * DD * KK;     // D*K*E
    float* out_ema    = out_cb     + (size_t)DD * KK * EE;     // D*K

    const size_t sm1 = (size_t)SM1_FLOATS * sizeof(float);
    cudaFuncSetAttribute(vq_k1, cudaFuncAttributeMaxDynamicSharedMemorySize, (int)sm1);

    // k0: decay bases (PDL-overlapped under k1)
    vq_k0<<<DD, 512>>>(codebook, ema, out_cb, out_ema);

    // k1 launched with programmatic dependent launch so it starts while k0 runs;
    // k1 gridsyncs before touching k0's outputs. Falls back to sequential order
    // semantics if PDL is unavailable.
    {
        cudaLaunchConfig_t cfg = {};
        cfg.gridDim  = dim3(DD * NH, 1, 1);
        cfg.blockDim = dim3(NT1, 1, 1);
        cfg.dynamicSmemBytes = sm1;
        cfg.stream = 0;
        cudaLaunchAttribute attr[1];
        attr[0].id = cudaLaunchAttributeProgrammaticStreamSerialization;
        attr[0].val.programmaticStreamSerializationAllowed = 1;
        cfg.attrs = attr;
        cfg.numAttrs = 1;
        cudaLaunchKernelEx(&cfg, vq_k1, cw_q, codebook, ema,
                           out_embed, out_onehot, out_cb, out_ema);
    }
}